// round 13
// baseline (speedup 1.0000x reference)
#include <cuda_runtime.h>

typedef unsigned long long ull;

__device__ __forceinline__ ull pack2(float lo, float hi) {
    ull r; asm("mov.b64 %0, {%1,%2};" : "=l"(r) : "f"(lo), "f"(hi)); return r;
}
__device__ __forceinline__ void unpack2(ull v, float &lo, float &hi) {
    asm("mov.b64 {%0,%1}, %2;" : "=f"(lo), "=f"(hi) : "l"(v));
}
__device__ __forceinline__ void fma2(ull &d, ull a, ull b) {
    asm("fma.rn.f32x2 %0, %1, %2, %0;" : "+l"(d) : "l"(a), "l"(b));
}
__device__ __forceinline__ unsigned smem_u32(const void* p) {
    unsigned a;
    asm("{ .reg .u64 tmp; cvta.to.shared.u64 tmp, %1; cvt.u32.u64 %0, tmp; }"
        : "=r"(a) : "l"(p));
    return a;
}

__global__ void __launch_bounds__(256, 4) attn_kernel(
    const float* __restrict__ S,
    const float* __restrict__ Wq,
    const float* __restrict__ bq,
    const float* __restrict__ Wk,
    const float* __restrict__ bk,
    float* __restrict__ out)
{
    // sBig: (1) XOR-swizzled S tile  (2) projection partials  (3) rotated compacted output
    __shared__ __align__(16) float sBig[8192];
    __shared__ __align__(16) float sW[128 * 16];   // [n][h]: h0..7=Wq, h8..15=Wk
    __shared__ __align__(16) float sQ[64 * 12];    // q[a][h0..7], f4 stride 3
    __shared__ __align__(16) float sK[64 * 12];    // kflat[a][h0..7], f4 stride 3
    __shared__ float sBias[16];

    const int t = threadIdx.x;
    const int w = t >> 5;
    const int l = t & 31;

    // ---- S stage via cp.async (LDGSTS): gmem -> swizzled smem, no reg round-trip ----
    {
        const float4* Sg = reinterpret_cast<const float4*>(S + (size_t)blockIdx.x * 8192);
        float4* sS4 = reinterpret_cast<float4*>(sBig);
        #pragma unroll
        for (int k = 0; k < 8; k++) {
            int g   = t + 256 * k;
            int row = g >> 5, c = g & 31;
            unsigned dst = smem_u32(&sS4[row * 32 + (c ^ (row & 31))]);
            asm volatile("cp.async.cg.shared.global [%0], [%1], 16;\n"
                         :: "r"(dst), "l"(Sg + g) : "memory");
        }
        asm volatile("cp.async.commit_group;\n" ::: "memory");
    }

    // ---- W + bias staged with normal LDG/STS in the cp.async shadow ----
    for (int idx = t; idx < 2048; idx += 256) {
        int n = idx >> 4, h = idx & 15;
        sW[idx] = (h < 8) ? Wq[n * 8 + h] : Wk[n * 8 + (h - 8)];
    }
    if (t < 16) sBias[t] = (t < 8) ? bq[t] : bk[t - 8];

    asm volatile("cp.async.wait_group 0;\n" ::: "memory");
    __syncthreads();

    // ---- preload this thread's S: rows {l, l+32}, chunks 4w..4w+3 ----
    float4 sv[2][4];
    {
        const float4* sS4 = reinterpret_cast<const float4*>(sBig);
        #pragma unroll
        for (int k2 = 0; k2 < 2; k2++)
            #pragma unroll
            for (int c4 = 0; c4 < 4; c4++)
                sv[k2][c4] = sS4[(l + 32 * k2) * 32 + ((4 * w + c4) ^ l)];
    }

    // ---- phase 2, half 0 (Q, h0..7): compute BEFORE the alias barrier ----
    ull acc0[2][4];
    #pragma unroll
    for (int k2 = 0; k2 < 2; k2++)
        #pragma unroll
        for (int p = 0; p < 4; p++) acc0[k2][p] = 0ull;
    #pragma unroll
    for (int c4 = 0; c4 < 4; c4++) {
        float a0[4] = {sv[0][c4].x, sv[0][c4].y, sv[0][c4].z, sv[0][c4].w};
        float a1[4] = {sv[1][c4].x, sv[1][c4].y, sv[1][c4].z, sv[1][c4].w};
        #pragma unroll
        for (int e = 0; e < 4; e++) {
            const ulonglong2* wp = reinterpret_cast<const ulonglong2*>(
                sW + (16 * w + 4 * c4 + e) * 16);
            ulonglong2 w0 = wp[0], w1 = wp[1];
            ull sA = pack2(a0[e], a0[e]);
            ull sB = pack2(a1[e], a1[e]);
            fma2(acc0[0][0], sA, w0.x); fma2(acc0[0][1], sA, w0.y);
            fma2(acc0[0][2], sA, w1.x); fma2(acc0[0][3], sA, w1.y);
            fma2(acc0[1][0], sB, w0.x); fma2(acc0[1][1], sB, w0.y);
            fma2(acc0[1][2], sB, w1.x); fma2(acc0[1][3], sB, w1.y);
        }
    }
    __syncthreads();   // all S reads done; sBig becomes the partial buffer

    {
        ulonglong2* P = reinterpret_cast<ulonglong2*>(sBig);
        // write half-0 partials (XOR-swizzled chunk index)
        #pragma unroll
        for (int k2 = 0; k2 < 2; k2++) {
            int row = l + 32 * k2;
            #pragma unroll
            for (int p = 0; p < 2; p++) {
                ulonglong2 vv;
                vv.x = acc0[k2][2 * p];
                vv.y = acc0[k2][2 * p + 1];
                P[(w * 64 + row) * 4 + (p ^ ((row >> 1) & 3))] = vv;
            }
        }

        // ---- phase 2, half 1 (K, h8..15) ----
        ull acc1[2][4];
        #pragma unroll
        for (int k2 = 0; k2 < 2; k2++)
            #pragma unroll
            for (int p = 0; p < 4; p++) acc1[k2][p] = 0ull;
        #pragma unroll
        for (int c4 = 0; c4 < 4; c4++) {
            float a0[4] = {sv[0][c4].x, sv[0][c4].y, sv[0][c4].z, sv[0][c4].w};
            float a1[4] = {sv[1][c4].x, sv[1][c4].y, sv[1][c4].z, sv[1][c4].w};
            #pragma unroll
            for (int e = 0; e < 4; e++) {
                const ulonglong2* wp = reinterpret_cast<const ulonglong2*>(
                    sW + (16 * w + 4 * c4 + e) * 16);
                ulonglong2 w0 = wp[2], w1 = wp[3];
                ull sA = pack2(a0[e], a0[e]);
                ull sB = pack2(a1[e], a1[e]);
                fma2(acc1[0][0], sA, w0.x); fma2(acc1[0][1], sA, w0.y);
                fma2(acc1[0][2], sA, w1.x); fma2(acc1[0][3], sA, w1.y);
                fma2(acc1[1][0], sB, w0.x); fma2(acc1[1][1], sB, w0.y);
                fma2(acc1[1][2], sB, w1.x); fma2(acc1[1][3], sB, w1.y);
            }
        }
        #pragma unroll
        for (int k2 = 0; k2 < 2; k2++) {
            int row = l + 32 * k2;
            #pragma unroll
            for (int p = 0; p < 2; p++) {
                ulonglong2 vv;
                vv.x = acc1[k2][2 * p];
                vv.y = acc1[k2][2 * p + 1];
                P[(w * 64 + row) * 4 + ((2 + p) ^ ((row >> 1) & 3))] = vv;
            }
        }
    }
    __syncthreads();

    // ---- reduce over 8 slices, add bias, write sQ / sK ----
    {
        const int a2 = t >> 2, c = t & 3;    // c: h-group {4c..4c+3}; c<2 -> q, c>=2 -> k
        const ulonglong2* P = reinterpret_cast<const ulonglong2*>(sBig);
        float r0 = 0.f, r1 = 0.f, r2 = 0.f, r3 = 0.f;
        #pragma unroll
        for (int s = 0; s < 8; s++) {
            ulonglong2 vv = P[(s * 64 + a2) * 4 + (c ^ ((a2 >> 1) & 3))];
            float x0, x1, y0, y1;
            unpack2(vv.x, x0, x1);
            unpack2(vv.y, y0, y1);
            r0 += x0; r1 += x1; r2 += y0; r3 += y1;
        }
        r0 += sBias[4 * c + 0]; r1 += sBias[4 * c + 1];
        r2 += sBias[4 * c + 2]; r3 += sBias[4 * c + 3];
        if (c < 2)
            reinterpret_cast<float4*>(sQ)[a2 * 3 + c] = make_float4(r0, r1, r2, r3);
        else
            reinterpret_cast<float4*>(sK)[a2 * 3 + (c - 2)] = make_float4(r0, r1, r2, r3);
    }
    __syncthreads();

    // ---- phase 3: thread = (ig: rows {2ig, 2ig+1}, jg8: j in [8*jg8, 8*jg8+8)) ----
    const int ig = t >> 3, jg8 = t & 7;
    float q[2][8];
    #pragma unroll
    for (int r = 0; r < 2; r++) {
        float4 qa = reinterpret_cast<const float4*>(sQ)[(2 * ig + r) * 3];
        float4 qb = reinterpret_cast<const float4*>(sQ)[(2 * ig + r) * 3 + 1];
        q[r][0] = qa.x; q[r][1] = qa.y; q[r][2] = qa.z; q[r][3] = qa.w;
        q[r][4] = qb.x; q[r][5] = qb.y; q[r][6] = qb.z; q[r][7] = qb.w;
    }
    ull accA[2][4];
    #pragma unroll
    for (int r = 0; r < 2; r++)
        #pragma unroll
        for (int c = 0; c < 4; c++) accA[r][c] = 0ull;
    #pragma unroll
    for (int h = 0; h < 8; h++) {
        const ulonglong2* kp = reinterpret_cast<const ulonglong2*>(sK);
        ulonglong2 k0 = kp[(8 * h + jg8) * 3];
        ulonglong2 k1 = kp[(8 * h + jg8) * 3 + 1];
        #pragma unroll
        for (int r = 0; r < 2; r++) {
            ull qq = pack2(q[r][h], q[r][h]);
            fma2(accA[r][0], qq, k0.x); fma2(accA[r][1], qq, k0.y);
            fma2(accA[r][2], qq, k1.x); fma2(accA[r][3], qq, k1.y);
        }
    }
    float v[2][8];
    #pragma unroll
    for (int r = 0; r < 2; r++) {
        unpack2(accA[r][0], v[r][0], v[r][1]);
        unpack2(accA[r][1], v[r][2], v[r][3]);
        unpack2(accA[r][2], v[r][4], v[r][5]);
        unpack2(accA[r][3], v[r][6], v[r][7]);
    }

    // ---- softmax over the 8 jg8 lanes (both rows interleaved for SHFL overlap) ----
    float mx[2], sm[2], inv[2];
    #pragma unroll
    for (int r = 0; r < 2; r++) {
        mx[r] = v[r][0];
        #pragma unroll
        for (int p = 1; p < 8; p++) mx[r] = fmaxf(mx[r], v[r][p]);
    }
    #pragma unroll
    for (int st = 1; st <= 4; st <<= 1) {
        mx[0] = fmaxf(mx[0], __shfl_xor_sync(0xffffffffu, mx[0], st));
        mx[1] = fmaxf(mx[1], __shfl_xor_sync(0xffffffffu, mx[1], st));
    }
    #pragma unroll
    for (int r = 0; r < 2; r++) {
        sm[r] = 0.f;
        #pragma unroll
        for (int p = 0; p < 8; p++) { v[r][p] = __expf(v[r][p] - mx[r]); sm[r] += v[r][p]; }
    }
    #pragma unroll
    for (int st = 1; st <= 4; st <<= 1) {
        sm[0] += __shfl_xor_sync(0xffffffffu, sm[0], st);
        sm[1] += __shfl_xor_sync(0xffffffffu, sm[1], st);
    }
    inv[0] = __fdividef(1.0f, sm[0]);
    inv[1] = __fdividef(1.0f, sm[1]);

    // ---- stage compacted rows at 65*i + jc + (jc>>5): conflict-broken scalar STS ----
    #pragma unroll
    for (int r = 0; r < 2; r++) {
        const int i = 2 * ig + r;
        float* orow = sBig + 65 * i;
        #pragma unroll
        for (int p = 0; p < 8; p++) {
            int j = 8 * jg8 + p;
            if (j != i) {
                int jc = j - (j > i);
                orow[jc + (jc >> 5)] = v[r][p] * inv[r];
            }
        }
    }
    __syncthreads();

    // ---- coalesced scalar copy: addr = o + 2*i + (jc>>5) ----
    {
        float* ob = out + (size_t)blockIdx.x * 4032;
        #pragma unroll
        for (int k = 0; k < 16; k++) {
            int o = t + 256 * k;
            if (k < 15 || t < 192) {
                int i  = (o * 66577) >> 22;     // o / 63, exact for o < 4096
                int jc = o - 63 * i;
                ob[o] = sBig[65 * i + jc + (jc >> 5)];
            }
        }
    }
}

extern "C" void kernel_launch(void* const* d_in, const int* in_sizes, int n_in,
                              void* d_out, int out_size)
{
    const float* S  = (const float*)d_in[0];
    const float* Wq = (const float*)d_in[1];
    const float* bq = (const float*)d_in[2];
    const float* Wk = (const float*)d_in[3];
    const float* bk = (const float*)d_in[4];
    int tb_total = in_sizes[0] / (64 * 128);   // 16384 tiles
    attn_kernel<<<tb_total, 256>>>(S, Wq, bq, Wk, bk, (float*)d_out);
}

// round 15
// speedup vs baseline: 1.0992x; 1.0992x over previous
#include <cuda_runtime.h>

typedef unsigned long long ull;

__device__ __forceinline__ ull pack2(float lo, float hi) {
    ull r; asm("mov.b64 %0, {%1,%2};" : "=l"(r) : "f"(lo), "f"(hi)); return r;
}
__device__ __forceinline__ void unpack2(ull v, float &lo, float &hi) {
    asm("mov.b64 {%0,%1}, %2;" : "=f"(lo), "=f"(hi) : "l"(v));
}
__device__ __forceinline__ void fma2(ull &d, ull a, ull b) {
    asm("fma.rn.f32x2 %0, %1, %2, %0;" : "+l"(d) : "l"(a), "l"(b));
}
__device__ __forceinline__ unsigned smem_u32(const void* p) {
    unsigned a;
    asm("{ .reg .u64 tmp; cvta.to.shared.u64 tmp, %1; cvt.u32.u64 %0, tmp; }"
        : "=r"(a) : "l"(p));
    return a;
}

__global__ void __launch_bounds__(256, 4) attn_kernel(
    const float* __restrict__ S,
    const float* __restrict__ Wq,
    const float* __restrict__ bq,
    const float* __restrict__ Wk,
    const float* __restrict__ bk,
    float* __restrict__ out)
{
    // sBig: (1) XOR-swizzled S tile  (2) projection partials  (3) compacted output
    __shared__ __align__(16) float sBig[8192];
    __shared__ __align__(16) float sW[128 * 16];   // [n][h]: h0..7=Wq, h8..15=Wk
    __shared__ __align__(16) float sQ[64 * 12];    // q[a][h0..7], f4 stride 3
    __shared__ __align__(16) float sK[64 * 12];    // kflat[a][h0..7], f4 stride 3
    __shared__ float sBias[16];

    const int t = threadIdx.x;
    const int w = t >> 5;
    const int l = t & 31;

    // ---- S stage via cp.async (LDGSTS): gmem -> swizzled smem, no reg round-trip ----
    {
        const float4* Sg = reinterpret_cast<const float4*>(S + (size_t)blockIdx.x * 8192);
        float4* sS4 = reinterpret_cast<float4*>(sBig);
        #pragma unroll
        for (int k = 0; k < 8; k++) {
            int g   = t + 256 * k;
            int row = g >> 5, c = g & 31;
            unsigned dst = smem_u32(&sS4[row * 32 + (c ^ (row & 31))]);
            asm volatile("cp.async.cg.shared.global [%0], [%1], 16;\n"
                         :: "r"(dst), "l"(Sg + g) : "memory");
        }
        asm volatile("cp.async.commit_group;\n" ::: "memory");
    }

    // ---- W (float4) + bias staged in the cp.async shadow ----
    {
        // Wq: 256 f4; thread t handles f4 g=t -> n=g>>1, hq=g&1 -> sW f4 idx 4n+hq
        const float4* wq4 = reinterpret_cast<const float4*>(Wq);
        const float4* wk4 = reinterpret_cast<const float4*>(Wk);
        float4* sW4 = reinterpret_cast<float4*>(sW);
        int n = t >> 1, hq = t & 1;
        sW4[4 * n + hq]     = wq4[t];
        sW4[4 * n + 2 + hq] = wk4[t];
    }
    if (t < 16) sBias[t] = (t < 8) ? bq[t] : bk[t - 8];

    asm volatile("cp.async.wait_group 0;\n" ::: "memory");
    __syncthreads();

    // ---- preload this thread's S: rows {l, l+32}, chunks 4w..4w+3 ----
    float4 sv[2][4];
    {
        const float4* sS4 = reinterpret_cast<const float4*>(sBig);
        #pragma unroll
        for (int k2 = 0; k2 < 2; k2++)
            #pragma unroll
            for (int c4 = 0; c4 < 4; c4++)
                sv[k2][c4] = sS4[(l + 32 * k2) * 32 + ((4 * w + c4) ^ l)];
    }

    // ---- phase 2, half 0 (Q, h0..7): compute BEFORE the alias barrier ----
    ull acc0[2][4];
    #pragma unroll
    for (int k2 = 0; k2 < 2; k2++)
        #pragma unroll
        for (int p = 0; p < 4; p++) acc0[k2][p] = 0ull;
    #pragma unroll
    for (int c4 = 0; c4 < 4; c4++) {
        float a0[4] = {sv[0][c4].x, sv[0][c4].y, sv[0][c4].z, sv[0][c4].w};
        float a1[4] = {sv[1][c4].x, sv[1][c4].y, sv[1][c4].z, sv[1][c4].w};
        #pragma unroll
        for (int e = 0; e < 4; e++) {
            const ulonglong2* wp = reinterpret_cast<const ulonglong2*>(
                sW + (16 * w + 4 * c4 + e) * 16);
            ulonglong2 w0 = wp[0], w1 = wp[1];
            ull sA = pack2(a0[e], a0[e]);
            ull sB = pack2(a1[e], a1[e]);
            fma2(acc0[0][0], sA, w0.x); fma2(acc0[0][1], sA, w0.y);
            fma2(acc0[0][2], sA, w1.x); fma2(acc0[0][3], sA, w1.y);
            fma2(acc0[1][0], sB, w0.x); fma2(acc0[1][1], sB, w0.y);
            fma2(acc0[1][2], sB, w1.x); fma2(acc0[1][3], sB, w1.y);
        }
    }
    __syncthreads();   // all S reads done; sBig becomes the partial buffer

    {
        ulonglong2* P = reinterpret_cast<ulonglong2*>(sBig);
        // write half-0 partials (XOR-swizzled chunk index)
        #pragma unroll
        for (int k2 = 0; k2 < 2; k2++) {
            int row = l + 32 * k2;
            #pragma unroll
            for (int p = 0; p < 2; p++) {
                ulonglong2 vv;
                vv.x = acc0[k2][2 * p];
                vv.y = acc0[k2][2 * p + 1];
                P[(w * 64 + row) * 4 + (p ^ ((row >> 1) & 3))] = vv;
            }
        }

        // ---- phase 2, half 1 (K, h8..15) ----
        ull acc1[2][4];
        #pragma unroll
        for (int k2 = 0; k2 < 2; k2++)
            #pragma unroll
            for (int p = 0; p < 4; p++) acc1[k2][p] = 0ull;
        #pragma unroll
        for (int c4 = 0; c4 < 4; c4++) {
            float a0[4] = {sv[0][c4].x, sv[0][c4].y, sv[0][c4].z, sv[0][c4].w};
            float a1[4] = {sv[1][c4].x, sv[1][c4].y, sv[1][c4].z, sv[1][c4].w};
            #pragma unroll
            for (int e = 0; e < 4; e++) {
                const ulonglong2* wp = reinterpret_cast<const ulonglong2*>(
                    sW + (16 * w + 4 * c4 + e) * 16);
                ulonglong2 w0 = wp[2], w1 = wp[3];
                ull sA = pack2(a0[e], a0[e]);
                ull sB = pack2(a1[e], a1[e]);
                fma2(acc1[0][0], sA, w0.x); fma2(acc1[0][1], sA, w0.y);
                fma2(acc1[0][2], sA, w1.x); fma2(acc1[0][3], sA, w1.y);
                fma2(acc1[1][0], sB, w0.x); fma2(acc1[1][1], sB, w0.y);
                fma2(acc1[1][2], sB, w1.x); fma2(acc1[1][3], sB, w1.y);
            }
        }
        #pragma unroll
        for (int k2 = 0; k2 < 2; k2++) {
            int row = l + 32 * k2;
            #pragma unroll
            for (int p = 0; p < 2; p++) {
                ulonglong2 vv;
                vv.x = acc1[k2][2 * p];
                vv.y = acc1[k2][2 * p + 1];
                P[(w * 64 + row) * 4 + ((2 + p) ^ ((row >> 1) & 3))] = vv;
            }
        }
    }
    __syncthreads();

    // ---- reduce over 8 slices, add bias, write sQ / sK ----
    {
        const int a2 = t >> 2, c = t & 3;    // c: h-group {4c..4c+3}; c<2 -> q, c>=2 -> k
        const ulonglong2* P = reinterpret_cast<const ulonglong2*>(sBig);
        float r0 = 0.f, r1 = 0.f, r2 = 0.f, r3 = 0.f;
        #pragma unroll
        for (int s = 0; s < 8; s++) {
            ulonglong2 vv = P[(s * 64 + a2) * 4 + (c ^ ((a2 >> 1) & 3))];
            float x0, x1, y0, y1;
            unpack2(vv.x, x0, x1);
            unpack2(vv.y, y0, y1);
            r0 += x0; r1 += x1; r2 += y0; r3 += y1;
        }
        r0 += sBias[4 * c + 0]; r1 += sBias[4 * c + 1];
        r2 += sBias[4 * c + 2]; r3 += sBias[4 * c + 3];
        if (c < 2)
            reinterpret_cast<float4*>(sQ)[a2 * 3 + c] = make_float4(r0, r1, r2, r3);
        else
            reinterpret_cast<float4*>(sK)[a2 * 3 + (c - 2)] = make_float4(r0, r1, r2, r3);
    }
    __syncthreads();

    // ---- phase 3: thread = (ig: rows {2ig, 2ig+1}, jg8: j in [8*jg8, 8*jg8+8)) ----
    const int ig = t >> 3, jg8 = t & 7;
    float q[2][8];
    #pragma unroll
    for (int r = 0; r < 2; r++) {
        float4 qa = reinterpret_cast<const float4*>(sQ)[(2 * ig + r) * 3];
        float4 qb = reinterpret_cast<const float4*>(sQ)[(2 * ig + r) * 3 + 1];
        q[r][0] = qa.x; q[r][1] = qa.y; q[r][2] = qa.z; q[r][3] = qa.w;
        q[r][4] = qb.x; q[r][5] = qb.y; q[r][6] = qb.z; q[r][7] = qb.w;
    }
    ull accA[2][4];
    #pragma unroll
    for (int r = 0; r < 2; r++)
        #pragma unroll
        for (int c = 0; c < 4; c++) accA[r][c] = 0ull;
    #pragma unroll
    for (int h = 0; h < 8; h++) {
        const ulonglong2* kp = reinterpret_cast<const ulonglong2*>(sK);
        ulonglong2 k0 = kp[(8 * h + jg8) * 3];
        ulonglong2 k1 = kp[(8 * h + jg8) * 3 + 1];
        #pragma unroll
        for (int r = 0; r < 2; r++) {
            ull qq = pack2(q[r][h], q[r][h]);
            fma2(accA[r][0], qq, k0.x); fma2(accA[r][1], qq, k0.y);
            fma2(accA[r][2], qq, k1.x); fma2(accA[r][3], qq, k1.y);
        }
    }
    float v[2][8];
    #pragma unroll
    for (int r = 0; r < 2; r++) {
        unpack2(accA[r][0], v[r][0], v[r][1]);
        unpack2(accA[r][1], v[r][2], v[r][3]);
        unpack2(accA[r][2], v[r][4], v[r][5]);
        unpack2(accA[r][3], v[r][6], v[r][7]);
    }

    // ---- softmax over the 8 jg8 lanes ----
    float inv[2];
    #pragma unroll
    for (int r = 0; r < 2; r++) {
        float mx = v[r][0];
        #pragma unroll
        for (int p = 1; p < 8; p++) mx = fmaxf(mx, v[r][p]);
        mx = fmaxf(mx, __shfl_xor_sync(0xffffffffu, mx, 1));
        mx = fmaxf(mx, __shfl_xor_sync(0xffffffffu, mx, 2));
        mx = fmaxf(mx, __shfl_xor_sync(0xffffffffu, mx, 4));
        float sm = 0.f;
        #pragma unroll
        for (int p = 0; p < 8; p++) { v[r][p] = __expf(v[r][p] - mx); sm += v[r][p]; }
        sm += __shfl_xor_sync(0xffffffffu, sm, 1);
        sm += __shfl_xor_sync(0xffffffffu, sm, 2);
        sm += __shfl_xor_sync(0xffffffffu, sm, 4);
        inv[r] = __fdividef(1.0f, sm);
    }

    // ---- stage COMPACTED rows: identical addresses to R11, but lanes with
    //      (jg8 & 4) write in p^4 order -> colliding lane pairs now hit
    //      banks ±4 apart => conflict-free STS. Values pre-permuted via FSEL.
    {
        const bool hi = (jg8 & 4);
        float vs[2][8];
        #pragma unroll
        for (int r = 0; r < 2; r++)
            #pragma unroll
            for (int p = 0; p < 8; p++)
                vs[r][p] = hi ? v[r][p ^ 4] : v[r][p];   // compile-time indices
        const int sx = hi ? 4 : 0;
        #pragma unroll
        for (int r = 0; r < 2; r++) {
            const int i = 2 * ig + r;
            float* orow = sBig + i * 63;
            #pragma unroll
            for (int p = 0; p < 8; p++) {
                int j = 8 * jg8 + (p ^ sx);
                if (j != i) orow[j - (j > i)] = vs[r][p] * inv[r];
            }
        }
    }
    __syncthreads();

    // ---- aligned float4 copy: smem -> gmem (4032 floats = 1008 f4) ----
    {
        float4* ob4 = reinterpret_cast<float4*>(out + (size_t)blockIdx.x * 4032);
        const float4* sb4 = reinterpret_cast<const float4*>(sBig);
        #pragma unroll
        for (int k = 0; k < 4; k++) {
            int o4 = t + 256 * k;
            if (o4 < 1008) ob4[o4] = sb4[o4];
        }
    }
}

extern "C" void kernel_launch(void* const* d_in, const int* in_sizes, int n_in,
                              void* d_out, int out_size)
{
    const float* S  = (const float*)d_in[0];
    const float* Wq = (const float*)d_in[1];
    const float* bq = (const float*)d_in[2];
    const float* Wk = (const float*)d_in[3];
    const float* bk = (const float*)d_in[4];
    int tb_total = in_sizes[0] / (64 * 128);   // 16384 tiles
    attn_kernel<<<tb_total, 256>>>(S, Wq, bq, Wk, bk, (float*)d_out);
}

// round 17
// speedup vs baseline: 1.1197x; 1.0187x over previous
#include <cuda_runtime.h>

typedef unsigned long long ull;

__device__ __forceinline__ ull pack2(float lo, float hi) {
    ull r; asm("mov.b64 %0, {%1,%2};" : "=l"(r) : "f"(lo), "f"(hi)); return r;
}
__device__ __forceinline__ void unpack2(ull v, float &lo, float &hi) {
    asm("mov.b64 {%0,%1}, %2;" : "=f"(lo), "=f"(hi) : "l"(v));
}
__device__ __forceinline__ void fma2(ull &d, ull a, ull b) {
    asm("fma.rn.f32x2 %0, %1, %2, %0;" : "+l"(d) : "l"(a), "l"(b));
}
__device__ __forceinline__ unsigned smem_u32(const void* p) {
    unsigned a;
    asm("{ .reg .u64 tmp; cvta.to.shared.u64 tmp, %1; cvt.u32.u64 %0, tmp; }"
        : "=r"(a) : "l"(p));
    return a;
}

__global__ void __launch_bounds__(256, 3) attn_kernel(
    const float* __restrict__ S,
    const float* __restrict__ Wq,
    const float* __restrict__ bq,
    const float* __restrict__ Wk,
    const float* __restrict__ bk,
    float* __restrict__ out)
{
    // sBig: (1) XOR-swizzled S tile  (2) projection partials  (3) compacted output
    __shared__ __align__(16) float sBig[8192];
    __shared__ __align__(16) float sW[128 * 16];   // [n][h]: h0..7=Wq, h8..15=Wk
    __shared__ __align__(16) float sQ[64 * 12];    // q[a][h0..7], f4 stride 3
    __shared__ __align__(16) float sK[64 * 12];    // kflat[a][h0..7], f4 stride 3
    __shared__ float sBias[16];

    const int t = threadIdx.x;
    const int w = t >> 5;
    const int l = t & 31;

    // ---- S stage via cp.async (LDGSTS): gmem -> swizzled smem ----
    {
        const float4* Sg = reinterpret_cast<const float4*>(S + (size_t)blockIdx.x * 8192);
        float4* sS4 = reinterpret_cast<float4*>(sBig);
        #pragma unroll
        for (int k = 0; k < 8; k++) {
            int g   = t + 256 * k;
            int row = g >> 5, c = g & 31;
            unsigned dst = smem_u32(&sS4[row * 32 + (c ^ (row & 31))]);
            asm volatile("cp.async.cg.shared.global [%0], [%1], 16;\n"
                         :: "r"(dst), "l"(Sg + g) : "memory");
        }
        asm volatile("cp.async.commit_group;\n" ::: "memory");
    }

    // ---- W (float4) + bias staged in the cp.async shadow ----
    {
        const float4* wq4 = reinterpret_cast<const float4*>(Wq);
        const float4* wk4 = reinterpret_cast<const float4*>(Wk);
        float4* sW4 = reinterpret_cast<float4*>(sW);
        int n = t >> 1, hq = t & 1;
        sW4[4 * n + hq]     = wq4[t];
        sW4[4 * n + 2 + hq] = wk4[t];
    }
    if (t < 16) sBias[t] = (t < 8) ? bq[t] : bk[t - 8];

    asm volatile("cp.async.wait_group 0;\n" ::: "memory");
    __syncthreads();

    // ---- phase 2: half-split mapping ----
    // lane: half = l>>4 (0: Q h0-7, 1: K h8-15), rl = l&15 -> rows {rl+16k}
    // warp w owns n in [16w, 16w+16)
    const int half = l >> 4;
    const int rl   = l & 15;

    ull acc[4][4];   // [row k][h-pair of this half]
    #pragma unroll
    for (int k = 0; k < 4; k++)
        #pragma unroll
        for (int p = 0; p < 4; p++) acc[k][p] = 0ull;

    {
        const float4* sS4 = reinterpret_cast<const float4*>(sBig);
        const float* wbase = sW + half * 8;
        #pragma unroll
        for (int pass = 0; pass < 2; pass++) {
            #pragma unroll
            for (int c = 0; c < 2; c++) {
                const int chunk = 4 * w + 2 * pass + c;
                float4 sv[4];
                #pragma unroll
                for (int k = 0; k < 4; k++) {
                    int row = rl + 16 * k;
                    sv[k] = sS4[row * 32 + (chunk ^ (row & 31))];
                }
                #pragma unroll
                for (int e = 0; e < 4; e++) {
                    const int n = 16 * w + 8 * pass + 4 * c + e;
                    const ulonglong2* wp =
                        reinterpret_cast<const ulonglong2*>(wbase + n * 16);
                    ulonglong2 wv0 = wp[0];   // h{0,1},{2,3} of this half
                    ulonglong2 wv1 = wp[1];   // h{4,5},{6,7}
                    #pragma unroll
                    for (int k = 0; k < 4; k++) {
                        float s = (e == 0) ? sv[k].x : (e == 1) ? sv[k].y
                                 : (e == 2) ? sv[k].z : sv[k].w;
                        ull ss = pack2(s, s);
                        fma2(acc[k][0], ss, wv0.x);
                        fma2(acc[k][1], ss, wv0.y);
                        fma2(acc[k][2], ss, wv1.x);
                        fma2(acc[k][3], ss, wv1.y);
                    }
                }
            }
        }
    }
    __syncthreads();   // all S reads done; sBig becomes the partial buffer

    // ---- write partials: chunk = (2*half + p) ^ ((row>>1)&3) — same layout as before ----
    {
        ulonglong2* P = reinterpret_cast<ulonglong2*>(sBig);
        #pragma unroll
        for (int k = 0; k < 4; k++) {
            int row = rl + 16 * k;
            #pragma unroll
            for (int p = 0; p < 2; p++) {
                ulonglong2 vv;
                vv.x = acc[k][2 * p];
                vv.y = acc[k][2 * p + 1];
                P[(w * 64 + row) * 4 + ((2 * half + p) ^ ((row >> 1) & 3))] = vv;
            }
        }
    }
    __syncthreads();

    // ---- reduce over 8 slices, add bias, write sQ / sK ----
    {
        const int a2 = t >> 2, c = t & 3;    // c: h-group {4c..4c+3}; c<2 -> q, c>=2 -> k
        const ulonglong2* P = reinterpret_cast<const ulonglong2*>(sBig);
        float r0 = 0.f, r1 = 0.f, r2 = 0.f, r3 = 0.f;
        #pragma unroll
        for (int s = 0; s < 8; s++) {
            ulonglong2 vv = P[(s * 64 + a2) * 4 + (c ^ ((a2 >> 1) & 3))];
            float x0, x1, y0, y1;
            unpack2(vv.x, x0, x1);
            unpack2(vv.y, y0, y1);
            r0 += x0; r1 += x1; r2 += y0; r3 += y1;
        }
        r0 += sBias[4 * c + 0]; r1 += sBias[4 * c + 1];
        r2 += sBias[4 * c + 2]; r3 += sBias[4 * c + 3];
        if (c < 2)
            reinterpret_cast<float4*>(sQ)[a2 * 3 + c] = make_float4(r0, r1, r2, r3);
        else
            reinterpret_cast<float4*>(sK)[a2 * 3 + (c - 2)] = make_float4(r0, r1, r2, r3);
    }
    __syncthreads();

    // ---- phase 3: thread = (ig: rows {2ig, 2ig+1}, jg8: j in [8*jg8, 8*jg8+8)) ----
    const int ig = t >> 3, jg8 = t & 7;
    float q[2][8];
    #pragma unroll
    for (int r = 0; r < 2; r++) {
        float4 qa = reinterpret_cast<const float4*>(sQ)[(2 * ig + r) * 3];
        float4 qb = reinterpret_cast<const float4*>(sQ)[(2 * ig + r) * 3 + 1];
        q[r][0] = qa.x; q[r][1] = qa.y; q[r][2] = qa.z; q[r][3] = qa.w;
        q[r][4] = qb.x; q[r][5] = qb.y; q[r][6] = qb.z; q[r][7] = qb.w;
    }
    ull accA[2][4];
    #pragma unroll
    for (int r = 0; r < 2; r++)
        #pragma unroll
        for (int c = 0; c < 4; c++) accA[r][c] = 0ull;
    #pragma unroll
    for (int h = 0; h < 8; h++) {
        const ulonglong2* kp = reinterpret_cast<const ulonglong2*>(sK);
        ulonglong2 k0 = kp[(8 * h + jg8) * 3];
        ulonglong2 k1 = kp[(8 * h + jg8) * 3 + 1];
        #pragma unroll
        for (int r = 0; r < 2; r++) {
            ull qq = pack2(q[r][h], q[r][h]);
            fma2(accA[r][0], qq, k0.x); fma2(accA[r][1], qq, k0.y);
            fma2(accA[r][2], qq, k1.x); fma2(accA[r][3], qq, k1.y);
        }
    }
    float v[2][8];
    #pragma unroll
    for (int r = 0; r < 2; r++) {
        unpack2(accA[r][0], v[r][0], v[r][1]);
        unpack2(accA[r][1], v[r][2], v[r][3]);
        unpack2(accA[r][2], v[r][4], v[r][5]);
        unpack2(accA[r][3], v[r][6], v[r][7]);
    }

    // ---- softmax over the 8 jg8 lanes ----
    float inv[2];
    #pragma unroll
    for (int r = 0; r < 2; r++) {
        float mx = v[r][0];
        #pragma unroll
        for (int p = 1; p < 8; p++) mx = fmaxf(mx, v[r][p]);
        mx = fmaxf(mx, __shfl_xor_sync(0xffffffffu, mx, 1));
        mx = fmaxf(mx, __shfl_xor_sync(0xffffffffu, mx, 2));
        mx = fmaxf(mx, __shfl_xor_sync(0xffffffffu, mx, 4));
        float sm = 0.f;
        #pragma unroll
        for (int p = 0; p < 8; p++) { v[r][p] = __expf(v[r][p] - mx); sm += v[r][p]; }
        sm += __shfl_xor_sync(0xffffffffu, sm, 1);
        sm += __shfl_xor_sync(0xffffffffu, sm, 2);
        sm += __shfl_xor_sync(0xffffffffu, sm, 4);
        inv[r] = __fdividef(1.0f, sm);
    }

    // ---- stage COMPACTED rows; lanes with (jg8 & 4) write in p^4 order ----
    {
        const bool hi = (jg8 & 4);
        float vs[2][8];
        #pragma unroll
        for (int r = 0; r < 2; r++)
            #pragma unroll
            for (int p = 0; p < 8; p++)
                vs[r][p] = hi ? v[r][p ^ 4] : v[r][p];
        const int sx = hi ? 4 : 0;
        #pragma unroll
        for (int r = 0; r < 2; r++) {
            const int i = 2 * ig + r;
            float* orow = sBig + i * 63;
            #pragma unroll
            for (int p = 0; p < 8; p++) {
                int j = 8 * jg8 + (p ^ sx);
                if (j != i) orow[j - (j > i)] = vs[r][p] * inv[r];
            }
        }
    }
    __syncthreads();

    // ---- aligned float4 copy: smem -> gmem (4032 floats = 1008 f4) ----
    {
        float4* ob4 = reinterpret_cast<float4*>(out + (size_t)blockIdx.x * 4032);
        const float4* sb4 = reinterpret_cast<const float4*>(sBig);
        #pragma unroll
        for (int k = 0; k < 4; k++) {
            int o4 = t + 256 * k;
            if (o4 < 1008) ob4[o4] = sb4[o4];
        }
    }
}

extern "C" void kernel_launch(void* const* d_in, const int* in_sizes, int n_in,
                              void* d_out, int out_size)
{
    const float* S  = (const float*)d_in[0];
    const float* Wq = (const float*)d_in[1];
    const float* bq = (const float*)d_in[2];
    const float* Wk = (const float*)d_in[3];
    const float* bk = (const float*)d_in[4];
    int tb_total = in_sizes[0] / (64 * 128);   // 16384 tiles
    attn_kernel<<<tb_total, 256>>>(S, Wq, bq, Wk, bk, (float*)d_out);
}